// round 6
// baseline (speedup 1.0000x reference)
#include <cuda_runtime.h>
#include <cuda_bf16.h>
#include <math.h>

// ---------------------------------------------------------------------------
// DLRM forward, fp32 baseline.
// Shapes: BATCH=16384, N_DENSE=13, M_SPA=64, NUM_TABLES=26, VOCAB=100000
// bottom: 13->512->256->64 (relu); interaction: 27x27 Gram lower-tri (351);
// top: 415->512->256->1 (sigmoid)
//
// NOTE: sparse_idx is declared int64 in the reference, but JAX without x64
// materializes it as int32 — read as const int*.
// ---------------------------------------------------------------------------

#define BATCH 16384
#define NTAB 26
#define MSPA 64
#define VOCAB 100000
#define H_LD 416        // padded leading dim for h (415 logical)

// Scratch (reused across stages; ~82 MB total, static device allocations)
__device__ float g_buf512[BATCH * 512];
__device__ float g_buf256[BATCH * 256];
__device__ float g_d[BATCH * 64];
__device__ float g_h[BATCH * H_LD];

// ---------------------------------------------------------------------------
// Generic tiled GEMM: C[M,N] = act(A[M,K] @ B[K,N] + bias), row-major all.
// 64x64 tile, TK=16, 256 threads, 4x4 per-thread microtile.
// ---------------------------------------------------------------------------
#define TM 64
#define TN 64
#define TK 16

template <bool RELU>
__global__ void __launch_bounds__(256) gemm_bias_kernel(
    const float* __restrict__ A, int lda,
    const float* __restrict__ B, int ldb,
    const float* __restrict__ bias,
    float* __restrict__ C, int ldc,
    int M, int N, int K)
{
    __shared__ __align__(16) float As[TK][TM + 4];   // row stride 68 floats
    __shared__ __align__(16) float Bs[TK][TN + 4];

    const int tid = threadIdx.x;
    const int tx = tid & 15;        // 16 cols of threads -> 4 C-cols each
    const int ty = tid >> 4;        // 16 rows of threads -> 4 C-rows each
    const int m0 = blockIdx.y * TM;
    const int n0 = blockIdx.x * TN;

    float acc[4][4] = {};

    for (int k0 = 0; k0 < K; k0 += TK) {
        // Load A tile (64 x 16): 4 elems/thread, coalesced along k within a row.
#pragma unroll
        for (int i = 0; i < 4; i++) {
            int e = tid + i * 256;
            int mm = e >> 4, kk = e & 15;
            int k = k0 + kk;
            As[kk][mm] = (k < K) ? A[(long long)(m0 + mm) * lda + k] : 0.f;
        }
        // Load B tile (16 x 64): coalesced along n.
#pragma unroll
        for (int i = 0; i < 4; i++) {
            int e = tid + i * 256;
            int kk = e >> 6, nn = e & 63;
            int k = k0 + kk;
            Bs[kk][nn] = (k < K) ? B[(long long)k * ldb + (n0 + nn)] : 0.f;
        }
        __syncthreads();

#pragma unroll
        for (int kk = 0; kk < TK; kk++) {
            float4 a4 = *(const float4*)&As[kk][ty * 4];
            float4 b4 = *(const float4*)&Bs[kk][tx * 4];
            float av[4] = {a4.x, a4.y, a4.z, a4.w};
            float bv[4] = {b4.x, b4.y, b4.z, b4.w};
#pragma unroll
            for (int i = 0; i < 4; i++)
#pragma unroll
                for (int j = 0; j < 4; j++)
                    acc[i][j] += av[i] * bv[j];
        }
        __syncthreads();
    }

#pragma unroll
    for (int i = 0; i < 4; i++) {
        int m = m0 + ty * 4 + i;
#pragma unroll
        for (int j = 0; j < 4; j++) {
            int n = n0 + tx * 4 + j;
            float v = acc[i][j] + bias[n];
            if (RELU) v = fmaxf(v, 0.f);
            C[(long long)m * ldc + n] = v;
        }
    }
}

// ---------------------------------------------------------------------------
// Interaction: per-sample CTA. Gather 26 embedding rows + bottom-MLP output d
// into k-major smem Tt[64][28] (pair-dot loads bank-conflict-free: within one
// unrolled-k step all lanes hit distinct columns i mod 32).
// Emit h[b] = [ d (64) | dot(T_i,T_j) for i>j in tril row-major order (351) ].
// ---------------------------------------------------------------------------
__global__ void __launch_bounds__(128) interact_kernel(
    const float* __restrict__ emb,
    const int* __restrict__ sidx,        // int32 (JAX x64-off downcast)
    const float* __restrict__ d,
    float* __restrict__ h)
{
    __shared__ float Tt[64][28];   // k-major, 27 used cols + 1 pad
    const int b = blockIdx.x;
    const int tid = threadIdx.x;

    // Gather 26 rows (coalesced 256B per row), store transposed.
    for (int e = tid; e < NTAB * 64; e += 128) {
        int t = e >> 6, k = e & 63;
        int v = sidx[b * NTAB + t];
        v = min(max(v, 0), VOCAB - 1);   // defensive clamp (real idx in range)
        Tt[k][t] = emb[((long long)t * VOCAB + v) * 64 + k];
    }
    float* hb = h + (long long)b * H_LD;
    if (tid < 64) {
        float dv = d[(long long)b * 64 + tid];
        Tt[tid][26] = dv;
        hb[tid] = dv;   // h[:, :64] = d
    }
    __syncthreads();

    // 351 strict-lower-tri pair dot products; p = i(i-1)/2 + j (row-major tril).
    for (int p = tid; p < 351; p += 128) {
        int i = (int)((1.0f + sqrtf((float)(1 + 8 * p))) * 0.5f);
        while (i * (i - 1) / 2 > p) i--;            // clamps for fp rounding
        while ((i + 1) * i / 2 <= p) i++;
        int j = p - i * (i - 1) / 2;

        float acc = 0.f;
#pragma unroll
        for (int k = 0; k < 64; k++)
            acc += Tt[k][i] * Tt[k][j];
        hb[64 + p] = acc;
    }
}

// ---------------------------------------------------------------------------
// Final layer: out[b] = sigmoid(dot(t1[b,:256], Wt2) + bt2). Warp per sample.
// ---------------------------------------------------------------------------
__global__ void __launch_bounds__(256) final_kernel(
    const float* __restrict__ t1,
    const float* __restrict__ W,     // [256,1]
    const float* __restrict__ bias,  // [1]
    float* __restrict__ out)
{
    int gwarp = (blockIdx.x * blockDim.x + threadIdx.x) >> 5;
    int lane = threadIdx.x & 31;
    if (gwarp >= BATCH) return;

    const float* row = t1 + (long long)gwarp * 256;
    float acc = 0.f;
#pragma unroll
    for (int k = 0; k < 256; k += 32)
        acc += row[k + lane] * W[k + lane];
#pragma unroll
    for (int o = 16; o; o >>= 1)
        acc += __shfl_xor_sync(0xffffffffu, acc, o);
    if (lane == 0)
        out[gwarp] = 1.f / (1.f + expf(-(acc + bias[0])));
}

// ---------------------------------------------------------------------------
// Launch sequence (graph-capturable: kernel launches only).
// ---------------------------------------------------------------------------
extern "C" void kernel_launch(void* const* d_in, const int* in_sizes, int n_in,
                              void* d_out, int out_size)
{
    const float* dense = (const float*)d_in[0];
    const int*   sidx  = (const int*)d_in[1];     // int32!
    const float* emb   = (const float*)d_in[2];
    const float* Wb0   = (const float*)d_in[3];
    const float* bb0   = (const float*)d_in[4];
    const float* Wb1   = (const float*)d_in[5];
    const float* bb1   = (const float*)d_in[6];
    const float* Wb2   = (const float*)d_in[7];
    const float* bb2   = (const float*)d_in[8];
    const float* Wt0   = (const float*)d_in[9];
    const float* bt0   = (const float*)d_in[10];
    const float* Wt1   = (const float*)d_in[11];
    const float* bt1   = (const float*)d_in[12];
    const float* Wt2   = (const float*)d_in[13];
    const float* bt2   = (const float*)d_in[14];
    float*       out   = (float*)d_out;

    float *buf512, *buf256, *dbot, *h;
    cudaGetSymbolAddress((void**)&buf512, g_buf512);
    cudaGetSymbolAddress((void**)&buf256, g_buf256);
    cudaGetSymbolAddress((void**)&dbot,   g_d);
    cudaGetSymbolAddress((void**)&h,      g_h);

    dim3 blk(256);

    // Bottom MLP
    gemm_bias_kernel<true><<<dim3(512 / TN, BATCH / TM), blk>>>(
        dense, 13, Wb0, 512, bb0, buf512, 512, BATCH, 512, 13);
    gemm_bias_kernel<true><<<dim3(256 / TN, BATCH / TM), blk>>>(
        buf512, 512, Wb1, 256, bb1, buf256, 256, BATCH, 256, 512);
    gemm_bias_kernel<true><<<dim3(64 / TN, BATCH / TM), blk>>>(
        buf256, 256, Wb2, 64, bb2, dbot, 64, BATCH, 64, 256);

    // Embedding gather + pairwise interaction -> h [BATCH, 415] (ld 416)
    interact_kernel<<<BATCH, 128>>>(emb, sidx, dbot, h);

    // Top MLP
    gemm_bias_kernel<true><<<dim3(512 / TN, BATCH / TM), blk>>>(
        h, H_LD, Wt0, 512, bt0, buf512, 512, BATCH, 512, 415);
    gemm_bias_kernel<true><<<dim3(256 / TN, BATCH / TM), blk>>>(
        buf512, 512, Wt1, 256, bt1, buf256, 256, BATCH, 256, 512);

    // Final dot + sigmoid
    final_kernel<<<(BATCH * 32 + 255) / 256, blk>>>(buf256, Wt2, bt2, out);
}

// round 8
// speedup vs baseline: 1.2577x; 1.2577x over previous
#include <cuda_runtime.h>
#include <cuda_bf16.h>
#include <math.h>

// ---------------------------------------------------------------------------
// DLRM forward. tf32 tensor-core GEMMs + mma-based interaction.
// BATCH=16384, N_DENSE=13, M_SPA=64, NUM_TABLES=26, VOCAB=100000
// bottom: 13->512->256->64 (relu); interaction: 27x27 Gram tril (351);
// top: 415->512->256->1 (sigmoid)
// sparse_idx materialized as int32 (JAX x64 off).
// ---------------------------------------------------------------------------

#define BATCH 16384
#define NTAB 26
#define VOCAB 100000
#define H_LD 416

__device__ float g_buf512[BATCH * 512];
__device__ float g_buf256[BATCH * 256];
__device__ float g_d[BATCH * 64];
__device__ float g_h[BATCH * H_LD];

// ---------------------------------------------------------------------------
// Helpers: tf32 convert + mma.m16n8k8 tf32
// ---------------------------------------------------------------------------
__device__ __forceinline__ unsigned f2tf32(float x) {
    unsigned r;
    asm("cvt.rna.tf32.f32 %0, %1;" : "=r"(r) : "f"(x));
    return r;
}

__device__ __forceinline__ void mma_tf32(float* c, const unsigned* a, const unsigned* b) {
    asm volatile(
        "mma.sync.aligned.m16n8k8.row.col.f32.tf32.tf32.f32 "
        "{%0,%1,%2,%3}, {%4,%5,%6,%7}, {%8,%9}, {%0,%1,%2,%3};\n"
        : "+f"(c[0]), "+f"(c[1]), "+f"(c[2]), "+f"(c[3])
        : "r"(a[0]), "r"(a[1]), "r"(a[2]), "r"(a[3]), "r"(b[0]), "r"(b[1]));
}

// ---------------------------------------------------------------------------
// Scalar GEMM (kept only for K=13 bottom layer).
// ---------------------------------------------------------------------------
#define TM 64
#define TN 64
#define TK 16

template <bool RELU>
__global__ void __launch_bounds__(256) gemm_bias_kernel(
    const float* __restrict__ A, int lda,
    const float* __restrict__ B, int ldb,
    const float* __restrict__ bias,
    float* __restrict__ C, int ldc,
    int M, int N, int K)
{
    __shared__ __align__(16) float As[TK][TM + 4];
    __shared__ __align__(16) float Bs[TK][TN + 4];

    const int tid = threadIdx.x;
    const int tx = tid & 15;
    const int ty = tid >> 4;
    const int m0 = blockIdx.y * TM;
    const int n0 = blockIdx.x * TN;

    float acc[4][4] = {};

    for (int k0 = 0; k0 < K; k0 += TK) {
#pragma unroll
        for (int i = 0; i < 4; i++) {
            int e = tid + i * 256;
            int mm = e >> 4, kk = e & 15;
            int k = k0 + kk;
            As[kk][mm] = (k < K) ? A[(long long)(m0 + mm) * lda + k] : 0.f;
        }
#pragma unroll
        for (int i = 0; i < 4; i++) {
            int e = tid + i * 256;
            int kk = e >> 6, nn = e & 63;
            int k = k0 + kk;
            Bs[kk][nn] = (k < K) ? B[(long long)k * ldb + (n0 + nn)] : 0.f;
        }
        __syncthreads();

#pragma unroll
        for (int kk = 0; kk < TK; kk++) {
            float4 a4 = *(const float4*)&As[kk][ty * 4];
            float4 b4 = *(const float4*)&Bs[kk][tx * 4];
            float av[4] = {a4.x, a4.y, a4.z, a4.w};
            float bv[4] = {b4.x, b4.y, b4.z, b4.w};
#pragma unroll
            for (int i = 0; i < 4; i++)
#pragma unroll
                for (int j = 0; j < 4; j++)
                    acc[i][j] += av[i] * bv[j];
        }
        __syncthreads();
    }

#pragma unroll
    for (int i = 0; i < 4; i++) {
        int m = m0 + ty * 4 + i;
#pragma unroll
        for (int j = 0; j < 4; j++) {
            int n = n0 + tx * 4 + j;
            float v = acc[i][j] + bias[n];
            if (RELU) v = fmaxf(v, 0.f);
            C[(long long)m * ldc + n] = v;
        }
    }
}

// ---------------------------------------------------------------------------
// tf32 tensor-core GEMM: C = act(A@B + bias). A row-major [M,K] (lda),
// B row-major [K,N] (ldb). BM=128, BN=64, BK=16; 8 warps in 4x2, 32x32/warp.
// Requires M%128==0, N%64==0 (true for all uses). K arbitrary (guarded).
// Smem pads chosen so fragment loads are bank-conflict-free:
//   As stride 20 (gid*20 mod 32 = {0,20,8,28,16,4,24,12} + tig -> 32 distinct)
//   Bs stride 72 (tig*72 mod 32 = {0,8,16,24} + gid -> distinct)
// ---------------------------------------------------------------------------
#define GBM 128
#define GBN 64
#define GBK 16

template <bool RELU>
__global__ void __launch_bounds__(256) gemm_tf32_kernel(
    const float* __restrict__ A, int lda,
    const float* __restrict__ B, int ldb,
    const float* __restrict__ bias,
    float* __restrict__ C, int ldc,
    int K)
{
    __shared__ __align__(16) unsigned As[GBM][20];
    __shared__ __align__(16) unsigned Bs[GBK][72];

    const int tid  = threadIdx.x;
    const int wid  = tid >> 5;
    const int lane = tid & 31;
    const int gid  = lane >> 2;   // 0..7
    const int tig  = lane & 3;    // 0..3
    const int wr   = wid >> 1;    // warp row 0..3
    const int wc   = wid & 1;     // warp col 0..1
    const int m0   = blockIdx.y * GBM;
    const int n0   = blockIdx.x * GBN;

    float acc[2][4][4];
#pragma unroll
    for (int mt = 0; mt < 2; mt++)
#pragma unroll
        for (int nt = 0; nt < 4; nt++)
#pragma unroll
            for (int r = 0; r < 4; r++) acc[mt][nt][r] = 0.f;

    for (int k0 = 0; k0 < K; k0 += GBK) {
        // A tile 128x16, 8 elems/thread (lanes -> consecutive k)
#pragma unroll
        for (int i = 0; i < 8; i++) {
            int e = tid + i * 256;
            int mm = e >> 4, kk = e & 15;
            int k = k0 + kk;
            float v = (k < K) ? A[(long long)(m0 + mm) * lda + k] : 0.f;
            As[mm][kk] = f2tf32(v);
        }
        // B tile 16x64, 4 elems/thread (lanes -> consecutive n)
#pragma unroll
        for (int i = 0; i < 4; i++) {
            int e = tid + i * 256;
            int kk = e >> 6, nn = e & 63;
            int k = k0 + kk;
            float v = (k < K) ? B[(long long)k * ldb + (n0 + nn)] : 0.f;
            Bs[kk][nn] = f2tf32(v);
        }
        __syncthreads();

#pragma unroll
        for (int ks = 0; ks < GBK; ks += 8) {
            unsigned a[2][4], bf[4][2];
#pragma unroll
            for (int mt = 0; mt < 2; mt++) {
                int row = wr * 32 + mt * 16 + gid;
                a[mt][0] = As[row][ks + tig];
                a[mt][1] = As[row + 8][ks + tig];
                a[mt][2] = As[row][ks + tig + 4];
                a[mt][3] = As[row + 8][ks + tig + 4];
            }
#pragma unroll
            for (int nt = 0; nt < 4; nt++) {
                int col = wc * 32 + nt * 8 + gid;
                bf[nt][0] = Bs[ks + tig][col];
                bf[nt][1] = Bs[ks + tig + 4][col];
            }
#pragma unroll
            for (int mt = 0; mt < 2; mt++)
#pragma unroll
                for (int nt = 0; nt < 4; nt++)
                    mma_tf32(acc[mt][nt], a[mt], bf[nt]);
        }
        __syncthreads();
    }

    // Epilogue: c0/c1 -> (row, 2tig / 2tig+1), c2/c3 -> (row+8, ...)
#pragma unroll
    for (int mt = 0; mt < 2; mt++) {
#pragma unroll
        for (int nt = 0; nt < 4; nt++) {
            int r0 = m0 + wr * 32 + mt * 16 + gid;
            int c0 = n0 + wc * 32 + nt * 8 + 2 * tig;
            float b0v = bias[c0], b1v = bias[c0 + 1];
            float v0 = acc[mt][nt][0] + b0v;
            float v1 = acc[mt][nt][1] + b1v;
            float v2 = acc[mt][nt][2] + b0v;
            float v3 = acc[mt][nt][3] + b1v;
            if (RELU) {
                v0 = fmaxf(v0, 0.f); v1 = fmaxf(v1, 0.f);
                v2 = fmaxf(v2, 0.f); v3 = fmaxf(v3, 0.f);
            }
            C[(long long)r0 * ldc + c0]           = v0;
            C[(long long)r0 * ldc + c0 + 1]       = v1;
            C[(long long)(r0 + 8) * ldc + c0]     = v2;
            C[(long long)(r0 + 8) * ldc + c0 + 1] = v3;
        }
    }
}

// ---------------------------------------------------------------------------
// Interaction via tensor cores. 4 samples/CTA, 1 warp/sample.
// Gather T (26 emb rows + d) into smem row-major [32][68] tf32 (rows 27..31
// zeroed), compute Z = T@T^T as a 32x32x64 mma GEMM, scatter tril entries.
// Fragment loads: addr = row*68+k, 68 mod 32 = 4 -> gid*4+tig covers 32
// distinct banks (conflict-free).
// ---------------------------------------------------------------------------
__global__ void __launch_bounds__(128) interact_mma_kernel(
    const float* __restrict__ emb,
    const int* __restrict__ sidx,
    const float* __restrict__ d,
    float* __restrict__ h)
{
    __shared__ unsigned Ts[4][32][68];   // 34816 B

    const int tid  = threadIdx.x;
    const int wid  = tid >> 5;
    const int lane = tid & 31;
    const int b0   = blockIdx.x * 4;

    // Gather 4*26 embedding rows (coalesced 256B rows).
    for (int e = tid; e < 4 * NTAB * 64; e += 128) {
        int s = e / (NTAB * 64);
        int r = e - s * (NTAB * 64);
        int t = r >> 6, k = r & 63;
        int v = sidx[(b0 + s) * NTAB + t];
        v = min(max(v, 0), VOCAB - 1);
        Ts[s][t][k] = f2tf32(emb[((long long)t * VOCAB + v) * 64 + k]);
    }
    // Row 26 = d; also copy d into h[:, :64]. Zero pad rows 27..31.
    for (int e = tid; e < 4 * 64; e += 128) {
        int s = e >> 6, k = e & 63;
        float dv = d[(long long)(b0 + s) * 64 + k];
        Ts[s][26][k] = f2tf32(dv);
        h[(long long)(b0 + s) * H_LD + k] = dv;
    }
    for (int e = tid; e < 4 * 5 * 64; e += 128) {
        int s = e / 320;
        int r = e - s * 320;
        Ts[s][27 + (r >> 6)][r & 63] = 0u;
    }
    __syncthreads();

    const int s   = wid;          // sample for this warp
    const int gid = lane >> 2;
    const int tig = lane & 3;

    float acc[2][4][4];
#pragma unroll
    for (int mt = 0; mt < 2; mt++)
#pragma unroll
        for (int nt = 0; nt < 4; nt++)
#pragma unroll
            for (int r = 0; r < 4; r++) acc[mt][nt][r] = 0.f;

#pragma unroll
    for (int kt = 0; kt < 8; kt++) {
        int k0 = kt * 8;
        unsigned a[2][4], bf[4][2];
#pragma unroll
        for (int mt = 0; mt < 2; mt++) {
            int row = mt * 16 + gid;
            a[mt][0] = Ts[s][row][k0 + tig];
            a[mt][1] = Ts[s][row + 8][k0 + tig];
            a[mt][2] = Ts[s][row][k0 + tig + 4];
            a[mt][3] = Ts[s][row + 8][k0 + tig + 4];
        }
#pragma unroll
        for (int nt = 0; nt < 4; nt++) {
            int cn = nt * 8 + gid;
            bf[nt][0] = Ts[s][cn][k0 + tig];
            bf[nt][1] = Ts[s][cn][k0 + tig + 4];
        }
#pragma unroll
        for (int mt = 0; mt < 2; mt++)
#pragma unroll
            for (int nt = 0; nt < 4; nt++)
                mma_tf32(acc[mt][nt], a[mt], bf[nt]);
    }

    // Scatter strict-lower-tri (i>j, i<=26): pos = i*(i-1)/2 + j.
    float* hb = h + (long long)(b0 + s) * H_LD;
#pragma unroll
    for (int mt = 0; mt < 2; mt++) {
#pragma unroll
        for (int nt = 0; nt < 4; nt++) {
            int i0 = mt * 16 + gid;
            int j0 = nt * 8 + 2 * tig;
#pragma unroll
            for (int r = 0; r < 4; r++) {
                int i = i0 + ((r >= 2) ? 8 : 0);
                int j = j0 + (r & 1);
                if (i <= 26 && j < i)
                    hb[64 + i * (i - 1) / 2 + j] = acc[mt][nt][r];
            }
        }
    }
}

// ---------------------------------------------------------------------------
// Final layer: sigmoid(dot(t1[b,:256], Wt2) + bt2). Warp per sample.
// ---------------------------------------------------------------------------
__global__ void __launch_bounds__(256) final_kernel(
    const float* __restrict__ t1,
    const float* __restrict__ W,
    const float* __restrict__ bias,
    float* __restrict__ out)
{
    int gwarp = (blockIdx.x * blockDim.x + threadIdx.x) >> 5;
    int lane = threadIdx.x & 31;
    if (gwarp >= BATCH) return;

    const float* row = t1 + (long long)gwarp * 256;
    float acc = 0.f;
#pragma unroll
    for (int k = 0; k < 256; k += 32)
        acc += row[k + lane] * W[k + lane];
#pragma unroll
    for (int o = 16; o; o >>= 1)
        acc += __shfl_xor_sync(0xffffffffu, acc, o);
    if (lane == 0)
        out[gwarp] = 1.f / (1.f + expf(-(acc + bias[0])));
}

// ---------------------------------------------------------------------------
// Launch sequence (graph-capturable).
// ---------------------------------------------------------------------------
extern "C" void kernel_launch(void* const* d_in, const int* in_sizes, int n_in,
                              void* d_out, int out_size)
{
    const float* dense = (const float*)d_in[0];
    const int*   sidx  = (const int*)d_in[1];
    const float* emb   = (const float*)d_in[2];
    const float* Wb0   = (const float*)d_in[3];
    const float* bb0   = (const float*)d_in[4];
    const float* Wb1   = (const float*)d_in[5];
    const float* bb1   = (const float*)d_in[6];
    const float* Wb2   = (const float*)d_in[7];
    const float* bb2   = (const float*)d_in[8];
    const float* Wt0   = (const float*)d_in[9];
    const float* bt0   = (const float*)d_in[10];
    const float* Wt1   = (const float*)d_in[11];
    const float* bt1   = (const float*)d_in[12];
    const float* Wt2   = (const float*)d_in[13];
    const float* bt2   = (const float*)d_in[14];
    float*       out   = (float*)d_out;

    float *buf512, *buf256, *dbot, *h;
    cudaGetSymbolAddress((void**)&buf512, g_buf512);
    cudaGetSymbolAddress((void**)&buf256, g_buf256);
    cudaGetSymbolAddress((void**)&dbot,   g_d);
    cudaGetSymbolAddress((void**)&h,      g_h);

    // Bottom MLP: K=13 layer scalar, rest tf32 tensor-core.
    gemm_bias_kernel<true><<<dim3(512 / TN, BATCH / TM), 256>>>(
        dense, 13, Wb0, 512, bb0, buf512, 512, BATCH, 512, 13);
    gemm_tf32_kernel<true><<<dim3(256 / GBN, BATCH / GBM), 256>>>(
        buf512, 512, Wb1, 256, bb1, buf256, 256, 512);
    gemm_tf32_kernel<true><<<dim3(64 / GBN, BATCH / GBM), 256>>>(
        buf256, 256, Wb2, 64, bb2, dbot, 64, 256);

    // Embedding gather + interaction (tensor-core Gram) -> h [BATCH, 415]
    interact_mma_kernel<<<BATCH / 4, 128>>>(emb, sidx, dbot, h);

    // Top MLP (tf32).
    gemm_tf32_kernel<true><<<dim3(512 / GBN, BATCH / GBM), 256>>>(
        h, H_LD, Wt0, 512, bt0, buf512, 512, 415);
    gemm_tf32_kernel<true><<<dim3(256 / GBN, BATCH / GBM), 256>>>(
        buf512, 512, Wt1, 256, bt1, buf256, 256, 512);

    // Final dot + sigmoid.
    final_kernel<<<(BATCH * 32 + 255) / 256, 256>>>(buf256, Wt2, bt2, out);
}